// round 5
// baseline (speedup 1.0000x reference)
#include <cuda_runtime.h>

// GAE reverse scan, 3-pass chunked linear recurrence, float2-vectorized.
//   adv_t = delta_t + c_t * adv_{t+1},  c_t = GL*(1-done_{t+1})
//   delta_t = r_t + GAMMA*v_{t+1}*(1-done_{t+1}) - v_t   (v_T=0, done_T=1)
// Output: d_out[0:T*N] = advantages, d_out[T*N:2*T*N] = advantages + values.

#define T_DIM   2048
#define N_DIM   4096
#define CT      64                  // chunks in time
#define LCH     (T_DIM / CT)        // 32 rows per chunk
#define BLOCK   256
#define N2      (N_DIM / 2)         // 2048 float2 columns
#define NGRP    (N2 / BLOCK)        // 8 column groups -> 512 blocks

#define GAMMA_F 0.99f
#define GL_F    (0.99f * 0.95f)

// Scratch: per-(chunk, column) affine aggregate (A,B) and carries. 3 MB.
__device__ float2 g_AB   [CT * N_DIM];
__device__ float  g_carry[CT * N_DIM];

// ---------------------------------------------------------------------------
// Pass 1: per-chunk affine reduction. adv_top = A + B * carry_in.
// ---------------------------------------------------------------------------
__global__ __launch_bounds__(BLOCK, 4)
void gae_pass1(const float2* __restrict__ rew,
               const float2* __restrict__ val,
               const float2* __restrict__ don)
{
    const int c2 = blockIdx.x * BLOCK + threadIdx.x;  // float2 column
    const int k  = blockIdx.y;
    const int lo = k * LCH;
    const int hi = lo + LCH - 1;

    float vnx, vny, dnx, dny;
    if (k == CT - 1) {
        vnx = 0.0f; vny = 0.0f; dnx = 1.0f; dny = 1.0f;
    } else {
        const float2 v2 = val[(size_t)(hi + 1) * N2 + c2];
        const float2 d2 = don[(size_t)(hi + 1) * N2 + c2];
        vnx = v2.x; vny = v2.y; dnx = d2.x; dny = d2.y;
    }

    float Ax = 0.0f, Ay = 0.0f, Bx = 1.0f, By = 1.0f;

    #pragma unroll
    for (int t = hi; t >= lo; --t) {
        const size_t idx = (size_t)t * N2 + c2;
        const float2 r2 = rew[idx];
        const float2 v2 = val[idx];
        const float2 d2 = don[idx];

        const float ntx = 1.0f - dnx;
        const float nty = 1.0f - dny;
        const float dex = fmaf(GAMMA_F * ntx, vnx, r2.x) - v2.x;
        const float dey = fmaf(GAMMA_F * nty, vny, r2.y) - v2.y;
        const float cx  = GL_F * ntx;
        const float cy  = GL_F * nty;

        Ax = fmaf(cx, Ax, dex);
        Ay = fmaf(cy, Ay, dey);
        Bx = cx * Bx;
        By = cy * By;

        vnx = v2.x; vny = v2.y; dnx = d2.x; dny = d2.y;
    }

    const int nbase = c2 * 2;
    g_AB[(size_t)k * N_DIM + nbase + 0] = make_float2(Ax, Bx);
    g_AB[(size_t)k * N_DIM + nbase + 1] = make_float2(Ay, By);
}

// ---------------------------------------------------------------------------
// Mid: per-column reverse fold over CT chunk aggregates -> carry per chunk.
// Loads are address-independent across k (only the FMA chain is serial).
// ---------------------------------------------------------------------------
__global__ __launch_bounds__(BLOCK)
void gae_mid()
{
    const int n = blockIdx.x * BLOCK + threadIdx.x;

    float carry = 0.0f;
    #pragma unroll
    for (int k = CT - 1; k >= 0; --k) {
        const size_t idx = (size_t)k * N_DIM + n;
        g_carry[idx] = carry;
        const float2 ab = g_AB[idx];
        carry = fmaf(ab.y, carry, ab.x);
    }
}

// ---------------------------------------------------------------------------
// Pass 2: re-scan each chunk seeded with its carry; emit adv & returns.
// ---------------------------------------------------------------------------
__global__ __launch_bounds__(BLOCK, 4)
void gae_pass2(const float2* __restrict__ rew,
               const float2* __restrict__ val,
               const float2* __restrict__ don,
               float2* __restrict__ out)
{
    const int c2 = blockIdx.x * BLOCK + threadIdx.x;
    const int k  = blockIdx.y;
    const int lo = k * LCH;
    const int hi = lo + LCH - 1;

    float vnx, vny, dnx, dny;
    if (k == CT - 1) {
        vnx = 0.0f; vny = 0.0f; dnx = 1.0f; dny = 1.0f;
    } else {
        const float2 v2 = val[(size_t)(hi + 1) * N2 + c2];
        const float2 d2 = don[(size_t)(hi + 1) * N2 + c2];
        vnx = v2.x; vny = v2.y; dnx = d2.x; dny = d2.y;
    }

    const int nbase = c2 * 2;
    float advx = g_carry[(size_t)k * N_DIM + nbase + 0];
    float advy = g_carry[(size_t)k * N_DIM + nbase + 1];

    float2* __restrict__ out_adv = out;
    float2* __restrict__ out_ret = out + (size_t)T_DIM * N2;

    #pragma unroll
    for (int t = hi; t >= lo; --t) {
        const size_t idx = (size_t)t * N2 + c2;
        const float2 r2 = rew[idx];
        const float2 v2 = val[idx];
        const float2 d2 = don[idx];

        const float ntx = 1.0f - dnx;
        const float nty = 1.0f - dny;
        const float dex = fmaf(GAMMA_F * ntx, vnx, r2.x) - v2.x;
        const float dey = fmaf(GAMMA_F * nty, vny, r2.y) - v2.y;
        const float cx  = GL_F * ntx;
        const float cy  = GL_F * nty;

        advx = fmaf(cx, advx, dex);
        advy = fmaf(cy, advy, dey);

        out_adv[idx] = make_float2(advx, advy);
        out_ret[idx] = make_float2(advx + v2.x, advy + v2.y);

        vnx = v2.x; vny = v2.y; dnx = d2.x; dny = d2.y;
    }
}

// ---------------------------------------------------------------------------
extern "C" void kernel_launch(void* const* d_in, const int* in_sizes, int n_in,
                              void* d_out, int out_size)
{
    const float2* rew = (const float2*)d_in[0];
    const float2* val = (const float2*)d_in[1];
    const float2* don = (const float2*)d_in[2];
    float2* out = (float2*)d_out;

    dim3 block(BLOCK);
    dim3 grid(NGRP, CT);          // 8 x 64 = 512 blocks

    gae_pass1<<<grid, block>>>(rew, val, don);
    gae_mid<<<N_DIM / BLOCK, block>>>();
    gae_pass2<<<grid, block>>>(rew, val, don, out);
}